// round 12
// baseline (speedup 1.0000x reference)
#include <cuda_runtime.h>
#include <cstdint>

#define BATCH        8192
#define CHAN         4096
#define KWIN         5
#define CH_TILE      1024          // channels per CTA (256 threads * 4)
#define THREADS      256
#define DEPTH        8             // stage ring slots
#define AHEAD        6             // rows in flight  (AHEAD + STEP <= DEPTH !)
#define STEP         2             // rows per barrier step
#define ROWS_PER_CTA 16
#define STAGE_F4     258           // float4 per stage: [halo_l][256 main][halo_r]
#define STAGE_STRIDE 264           // padded stage stride in float4

__device__ __forceinline__ void cp_async16(void* smem, const void* gmem) {
    unsigned s = (unsigned)__cvta_generic_to_shared(smem);
    asm volatile("cp.async.cg.shared.global [%0], [%1], 16;" :: "r"(s), "l"(gmem));
}
__device__ __forceinline__ void cp_commit() {
    asm volatile("cp.async.commit_group;");
}
template <int N>
__device__ __forceinline__ void cp_wait() {
    asm volatile("cp.async.wait_group %0;" :: "n"(N));
}

// out[b,i] = sum_k W[i,k] * x[b, i+k-2] (zero-padded) + bias[i]
// CTA-wide cp.async pipeline (R6-proven: DEPTH=8, AHEAD=6, STEP=2) with
// 16 rows/CTA -> grid=2048 -> ~2.77 waves, small tail (was 1.38 waves).
// Safety invariant: AHEAD + STEP <= DEPTH, so each refill targets a stage
// whose reads completed in the PREVIOUS step (ordered by __syncthreads).
__global__ __launch_bounds__(THREADS) void grouped_linear_kernel(
    const float* __restrict__ x,
    const float* __restrict__ W,
    const float* __restrict__ bias,
    float* __restrict__ out)
{
    __shared__ float4 smem[DEPTH * STAGE_STRIDE];   // 33792 B

    const int t    = threadIdx.x;
    const int c0   = blockIdx.x * CH_TILE;
    const int c    = c0 + t * 4;
    const int row0 = blockIdx.y * ROWS_PER_CTA;

    const bool not_first_tile = (blockIdx.x > 0);
    const bool not_last_tile  = (c0 + CH_TILE < CHAN);

    // ---- per-thread constants: W[c..c+3][0..4] (20 floats) + bias ----
    const float4* wv = reinterpret_cast<const float4*>(W + (size_t)c * KWIN);
    const float4 wa = wv[0];
    const float4 wb = wv[1];
    const float4 wc = wv[2];
    const float4 wd = wv[3];
    const float4 we = wv[4];
    const float4 bb = *reinterpret_cast<const float4*>(bias + c);

    // zero halo slots once (edge tiles never overwrite them)
    if (t < DEPTH) {
        smem[t * STAGE_STRIDE + 0]            = make_float4(0.f, 0.f, 0.f, 0.f);
        smem[t * STAGE_STRIDE + STAGE_F4 - 1] = make_float4(0.f, 0.f, 0.f, 0.f);
    }
    __syncthreads();

    const float4* gbase = reinterpret_cast<const float4*>(x + (size_t)row0 * CHAN + c0 - 4);
    const size_t  grow  = CHAN / 4;

    auto load_stage = [&](int r) {                      // stage = r % DEPTH
        float4* sp = smem + (r & (DEPTH - 1)) * STAGE_STRIDE;
        const float4* gp = gbase + (size_t)r * grow;
        cp_async16(sp + t + 1, gp + t + 1);
        if (t == 0 && not_first_tile) cp_async16(sp, gp);
        if (t == 1 && not_last_tile)  cp_async16(sp + 257, gp + 257);
    };

    auto do_row = [&](int r, float* op) {
        const float4* sp = smem + (r & (DEPTH - 1)) * STAGE_STRIDE;
        const float4 s0 = sp[t];
        const float4 s1 = sp[t + 1];
        const float4 s2 = sp[t + 2];
        const float xm2 = s0.z, xm1 = s0.w;
        const float xp4 = s2.x, xp5 = s2.y;

        float4 o;
        o.x = fmaf(wa.x, xm2,  fmaf(wa.y, xm1,  fmaf(wa.z, s1.x,
              fmaf(wa.w, s1.y, fmaf(wb.x, s1.z, bb.x)))));
        o.y = fmaf(wb.y, xm1,  fmaf(wb.z, s1.x, fmaf(wb.w, s1.y,
              fmaf(wc.x, s1.z, fmaf(wc.y, s1.w, bb.y)))));
        o.z = fmaf(wc.z, s1.x, fmaf(wc.w, s1.y, fmaf(wd.x, s1.z,
              fmaf(wd.y, s1.w, fmaf(wd.z, xp4,  bb.z)))));
        o.w = fmaf(wd.w, s1.y, fmaf(we.x, s1.z, fmaf(we.y, s1.w,
              fmaf(we.z, xp4,  fmaf(we.w, xp5,  bb.w)))));
        __stcs(reinterpret_cast<float4*>(op), o);
    };

    // ---- prologue: rows 0..AHEAD-1, one commit group each ----
#pragma unroll
    for (int r = 0; r < AHEAD; r++) {
        load_stage(r);
        cp_commit();
    }

    float* op = out + (size_t)row0 * CHAN + c;

#pragma unroll
    for (int i = 0; i < ROWS_PER_CTA; i += STEP) {
        cp_wait<AHEAD - STEP>();       // rows i..i+STEP-1 complete (this thread)
        __syncthreads();               // all threads; orders prior-step reads
                                       // before the refills below

        // refill the stages consumed LAST step
#pragma unroll
        for (int j = 0; j < STEP; j++) {
            const int nr = i + AHEAD + j;
            if (nr < ROWS_PER_CTA) load_stage(nr);
            cp_commit();               // unconditional: keeps group counts fixed
        }

#pragma unroll
        for (int j = 0; j < STEP; j++)
            do_row(i + j, op + (size_t)j * CHAN);
        op += (size_t)STEP * CHAN;
    }
}

extern "C" void kernel_launch(void* const* d_in, const int* in_sizes, int n_in,
                              void* d_out, int out_size)
{
    const float* x    = (const float*)d_in[0];
    const float* W    = (const float*)d_in[1];
    const float* bias = (const float*)d_in[2];
    float* out        = (float*)d_out;

    dim3 block(THREADS);
    dim3 grid(CHAN / CH_TILE, BATCH / ROWS_PER_CTA);  // (4, 512) = 2048 CTAs
    grouped_linear_kernel<<<grid, block>>>(x, W, bias, out);
}

// round 14
// speedup vs baseline: 1.0095x; 1.0095x over previous
#include <cuda_runtime.h>
#include <cstdint>

#define BATCH        8192
#define CHAN         4096
#define KWIN         5
#define CH_TILE      1024          // channels per CTA (256 threads * 4)
#define THREADS      256
#define DEPTH        12            // stage ring slots
#define AHEAD        10            // rows in flight  (AHEAD + STEP <= DEPTH !)
#define STEP         2             // rows per barrier step
#define ROWS_PER_CTA 32
#define STAGE_F4     258           // float4 per stage: [halo_l][256 main][halo_r]
#define STAGE_STRIDE 264           // padded stage stride in float4 (4224 B)

__device__ __forceinline__ void cp_async16(void* smem, const void* gmem) {
    unsigned s = (unsigned)__cvta_generic_to_shared(smem);
    asm volatile("cp.async.cg.shared.global [%0], [%1], 16;" :: "r"(s), "l"(gmem));
}
__device__ __forceinline__ void cp_commit() {
    asm volatile("cp.async.commit_group;");
}
template <int N>
__device__ __forceinline__ void cp_wait() {
    asm volatile("cp.async.wait_group %0;" :: "n"(N));
}

// out[b,i] = sum_k W[i,k] * x[b, i+k-2] (zero-padded) + bias[i]
// CTA-wide cp.async pipeline, 12-stage ring, 10 rows (~42KB/CTA) in flight.
// Safety invariant: AHEAD + STEP <= DEPTH -> every refill targets a stage
// whose reads finished in the PREVIOUS step (ordered by __syncthreads).
__global__ __launch_bounds__(THREADS) void grouped_linear_kernel(
    const float* __restrict__ x,
    const float* __restrict__ W,
    const float* __restrict__ bias,
    float* __restrict__ out)
{
    __shared__ float4 smem[DEPTH * STAGE_STRIDE];   // 50688 B

    const int t    = threadIdx.x;
    const int c0   = blockIdx.x * CH_TILE;
    const int c    = c0 + t * 4;
    const int row0 = blockIdx.y * ROWS_PER_CTA;

    const bool not_first_tile = (blockIdx.x > 0);
    const bool not_last_tile  = (c0 + CH_TILE < CHAN);

    // ---- per-thread constants: W[c..c+3][0..4] (20 floats) + bias ----
    const float4* wv = reinterpret_cast<const float4*>(W + (size_t)c * KWIN);
    const float4 wa = wv[0];
    const float4 wb = wv[1];
    const float4 wc = wv[2];
    const float4 wd = wv[3];
    const float4 we = wv[4];
    const float4 bb = *reinterpret_cast<const float4*>(bias + c);

    // zero halo slots once (edge tiles never overwrite them)
    if (t < DEPTH) {
        smem[t * STAGE_STRIDE + 0]            = make_float4(0.f, 0.f, 0.f, 0.f);
        smem[t * STAGE_STRIDE + STAGE_F4 - 1] = make_float4(0.f, 0.f, 0.f, 0.f);
    }
    __syncthreads();

    const float4* gbase = reinterpret_cast<const float4*>(x + (size_t)row0 * CHAN + c0 - 4);
    const size_t  grow  = CHAN / 4;

    // writer/reader walk the stage ring with explicit wrapping counters
    auto load_stage = [&](int stage, int r) {
        float4* sp = smem + stage * STAGE_STRIDE;
        const float4* gp = gbase + (size_t)r * grow;
        cp_async16(sp + t + 1, gp + t + 1);
        if (t == 0 && not_first_tile) cp_async16(sp, gp);
        if (t == 1 && not_last_tile)  cp_async16(sp + 257, gp + 257);
    };

    auto do_row = [&](int stage, float* op) {
        const float4* sp = smem + stage * STAGE_STRIDE;
        const float4 s0 = sp[t];
        const float4 s1 = sp[t + 1];
        const float4 s2 = sp[t + 2];
        const float xm2 = s0.z, xm1 = s0.w;
        const float xp4 = s2.x, xp5 = s2.y;

        float4 o;
        o.x = fmaf(wa.x, xm2,  fmaf(wa.y, xm1,  fmaf(wa.z, s1.x,
              fmaf(wa.w, s1.y, fmaf(wb.x, s1.z, bb.x)))));
        o.y = fmaf(wb.y, xm1,  fmaf(wb.z, s1.x, fmaf(wb.w, s1.y,
              fmaf(wc.x, s1.z, fmaf(wc.y, s1.w, bb.y)))));
        o.z = fmaf(wc.z, s1.x, fmaf(wc.w, s1.y, fmaf(wd.x, s1.z,
              fmaf(wd.y, s1.w, fmaf(wd.z, xp4,  bb.z)))));
        o.w = fmaf(wd.w, s1.y, fmaf(we.x, s1.z, fmaf(we.y, s1.w,
              fmaf(we.z, xp4,  fmaf(we.w, xp5,  bb.w)))));
        *reinterpret_cast<float4*>(op) = o;   // plain store: let L2 defer writeback
    };

    int ld_stage = 0;   // next stage to write
    int rd_stage = 0;   // next stage to read

    // ---- prologue: rows 0..AHEAD-1, one commit group each ----
#pragma unroll
    for (int r = 0; r < AHEAD; r++) {
        load_stage(ld_stage, r);
        cp_commit();
        ld_stage = (ld_stage == DEPTH - 1) ? 0 : ld_stage + 1;
    }

    float* op = out + (size_t)row0 * CHAN + c;

#pragma unroll
    for (int i = 0; i < ROWS_PER_CTA; i += STEP) {
        cp_wait<AHEAD - STEP>();       // rows i..i+STEP-1 complete (this thread)
        __syncthreads();               // all threads; orders prior-step reads
                                       // before the refills below

        // refill the stages consumed LAST step
#pragma unroll
        for (int j = 0; j < STEP; j++) {
            const int nr = i + AHEAD + j;
            if (nr < ROWS_PER_CTA) load_stage(ld_stage, nr);
            cp_commit();               // unconditional: keeps group counts fixed
            ld_stage = (ld_stage == DEPTH - 1) ? 0 : ld_stage + 1;
        }

#pragma unroll
        for (int j = 0; j < STEP; j++) {
            do_row(rd_stage, op + (size_t)j * CHAN);
            rd_stage = (rd_stage == DEPTH - 1) ? 0 : rd_stage + 1;
        }
        op += (size_t)STEP * CHAN;
    }
}

extern "C" void kernel_launch(void* const* d_in, const int* in_sizes, int n_in,
                              void* d_out, int out_size)
{
    const float* x    = (const float*)d_in[0];
    const float* W    = (const float*)d_in[1];
    const float* bias = (const float*)d_in[2];
    float* out        = (float*)d_out;

    dim3 block(THREADS);
    dim3 grid(CHAN / CH_TILE, BATCH / ROWS_PER_CTA);  // (4, 256) = 1024 CTAs
    grouped_linear_kernel<<<grid, block>>>(x, W, bias, out);
}

// round 16
// speedup vs baseline: 1.0102x; 1.0007x over previous
#include <cuda_runtime.h>
#include <cstdint>

#define BATCH        8192
#define CHAN         4096
#define KWIN         5
#define CH_TILE      1024          // channels per CTA (256 threads * 4)
#define THREADS      256
#define DEPTH        12            // stage ring slots
#define AHEAD        10            // rows in flight  (AHEAD + STEP <= DEPTH !)
#define STEP         2             // rows per barrier step
#define ROWS_PER_CTA 32
#define STAGE_F4     258           // float4 per stage: [halo_l][256 main][halo_r]
#define STAGE_STRIDE 264           // padded stage stride in float4 (4224 B)

// cp.async with L2 evict_last cache hint: keeps x resident in the 126MB L2
// across graph replays (x is 128MB -> fractional 0.875 avoids sweep-thrash).
__device__ __forceinline__ void cp_async16_hint(void* smem, const void* gmem,
                                                uint64_t policy) {
    unsigned s = (unsigned)__cvta_generic_to_shared(smem);
    asm volatile("cp.async.cg.shared.global.L2::cache_hint [%0], [%1], 16, %2;"
                 :: "r"(s), "l"(gmem), "l"(policy));
}
__device__ __forceinline__ uint64_t make_evict_last_policy() {
    uint64_t p;
    asm volatile("createpolicy.fractional.L2::evict_last.b64 %0, 0.875;" : "=l"(p));
    return p;
}
__device__ __forceinline__ void cp_commit() {
    asm volatile("cp.async.commit_group;");
}
template <int N>
__device__ __forceinline__ void cp_wait() {
    asm volatile("cp.async.wait_group %0;" :: "n"(N));
}

// out[b,i] = sum_k W[i,k] * x[b, i+k-2] (zero-padded) + bias[i]
// R14-proven pipeline (12-stage ring, 10 rows in flight, AHEAD+STEP<=DEPTH)
// + L2 steering: x reads evict_last (sticky across replays), out stores
// evict_first (__stcs) so the write stream doesn't evict x.
__global__ __launch_bounds__(THREADS) void grouped_linear_kernel(
    const float* __restrict__ x,
    const float* __restrict__ W,
    const float* __restrict__ bias,
    float* __restrict__ out)
{
    __shared__ float4 smem[DEPTH * STAGE_STRIDE];   // 50688 B

    const int t    = threadIdx.x;
    const int c0   = blockIdx.x * CH_TILE;
    const int c    = c0 + t * 4;
    const int row0 = blockIdx.y * ROWS_PER_CTA;

    const bool not_first_tile = (blockIdx.x > 0);
    const bool not_last_tile  = (c0 + CH_TILE < CHAN);

    const uint64_t pol = make_evict_last_policy();

    // ---- per-thread constants: W[c..c+3][0..4] (20 floats) + bias ----
    const float4* wv = reinterpret_cast<const float4*>(W + (size_t)c * KWIN);
    const float4 wa = wv[0];
    const float4 wb = wv[1];
    const float4 wc = wv[2];
    const float4 wd = wv[3];
    const float4 we = wv[4];
    const float4 bb = *reinterpret_cast<const float4*>(bias + c);

    // zero halo slots once (edge tiles never overwrite them)
    if (t < DEPTH) {
        smem[t * STAGE_STRIDE + 0]            = make_float4(0.f, 0.f, 0.f, 0.f);
        smem[t * STAGE_STRIDE + STAGE_F4 - 1] = make_float4(0.f, 0.f, 0.f, 0.f);
    }
    __syncthreads();

    const float4* gbase = reinterpret_cast<const float4*>(x + (size_t)row0 * CHAN + c0 - 4);
    const size_t  grow  = CHAN / 4;

    auto load_stage = [&](int stage, int r) {
        float4* sp = smem + stage * STAGE_STRIDE;
        const float4* gp = gbase + (size_t)r * grow;
        cp_async16_hint(sp + t + 1, gp + t + 1, pol);
        if (t == 0 && not_first_tile) cp_async16_hint(sp, gp, pol);
        if (t == 1 && not_last_tile)  cp_async16_hint(sp + 257, gp + 257, pol);
    };

    auto do_row = [&](int stage, float* op) {
        const float4* sp = smem + stage * STAGE_STRIDE;
        const float4 s0 = sp[t];
        const float4 s1 = sp[t + 1];
        const float4 s2 = sp[t + 2];
        const float xm2 = s0.z, xm1 = s0.w;
        const float xp4 = s2.x, xp5 = s2.y;

        float4 o;
        o.x = fmaf(wa.x, xm2,  fmaf(wa.y, xm1,  fmaf(wa.z, s1.x,
              fmaf(wa.w, s1.y, fmaf(wb.x, s1.z, bb.x)))));
        o.y = fmaf(wb.y, xm1,  fmaf(wb.z, s1.x, fmaf(wb.w, s1.y,
              fmaf(wc.x, s1.z, fmaf(wc.y, s1.w, bb.y)))));
        o.z = fmaf(wc.z, s1.x, fmaf(wc.w, s1.y, fmaf(wd.x, s1.z,
              fmaf(wd.y, s1.w, fmaf(wd.z, xp4,  bb.z)))));
        o.w = fmaf(wd.w, s1.y, fmaf(we.x, s1.z, fmaf(we.y, s1.w,
              fmaf(we.z, xp4,  fmaf(we.w, xp5,  bb.w)))));
        __stcs(reinterpret_cast<float4*>(op), o);   // evict-first: protect x in L2
    };

    int ld_stage = 0;   // next stage to write
    int rd_stage = 0;   // next stage to read

    // ---- prologue: rows 0..AHEAD-1, one commit group each ----
#pragma unroll
    for (int r = 0; r < AHEAD; r++) {
        load_stage(ld_stage, r);
        cp_commit();
        ld_stage = (ld_stage == DEPTH - 1) ? 0 : ld_stage + 1;
    }

    float* op = out + (size_t)row0 * CHAN + c;

#pragma unroll
    for (int i = 0; i < ROWS_PER_CTA; i += STEP) {
        cp_wait<AHEAD - STEP>();       // rows i..i+STEP-1 complete (this thread)
        __syncthreads();               // all threads; orders prior-step reads
                                       // before the refills below

        // refill the stages consumed LAST step
#pragma unroll
        for (int j = 0; j < STEP; j++) {
            const int nr = i + AHEAD + j;
            if (nr < ROWS_PER_CTA) load_stage(ld_stage, nr);
            cp_commit();               // unconditional: keeps group counts fixed
            ld_stage = (ld_stage == DEPTH - 1) ? 0 : ld_stage + 1;
        }

#pragma unroll
        for (int j = 0; j < STEP; j++) {
            do_row(rd_stage, op + (size_t)j * CHAN);
            rd_stage = (rd_stage == DEPTH - 1) ? 0 : rd_stage + 1;
        }
        op += (size_t)STEP * CHAN;
    }
}

extern "C" void kernel_launch(void* const* d_in, const int* in_sizes, int n_in,
                              void* d_out, int out_size)
{
    const float* x    = (const float*)d_in[0];
    const float* W    = (const float*)d_in[1];
    const float* bias = (const float*)d_in[2];
    float* out        = (float*)d_out;

    dim3 block(THREADS);
    dim3 grid(CHAN / CH_TILE, BATCH / ROWS_PER_CTA);  // (4, 256) = 1024 CTAs
    grouped_linear_kernel<<<grid, block>>>(x, W, bias, out);
}